// round 17
// baseline (speedup 1.0000x reference)
#include <cuda_runtime.h>
#include <cuda_bf16.h>
#include <cstdint>
#include <math_constants.h>

#define BATCH 2
#define LV 1920
#define LT 128
#define LSEQ 2048
#define NTOK 4096
#define NH 12
#define HD 128
#define DIMIN 1536
#define QKVN 4608
#define EPSV 1e-6f

// ---------------- scratch ----------------
__device__ float g_qkv[(size_t)NTOK * QKVN];
__device__ __nv_bfloat16 g_q[(size_t)BATCH * NH * LSEQ * HD];
__device__ __nv_bfloat16 g_k[(size_t)BATCH * NH * LSEQ * HD];
__device__ __nv_bfloat16 g_v[(size_t)BATCH * NH * LSEQ * HD];
__device__ float g_attn[(size_t)NTOK * DIMIN];

// ---------------- PTX helpers ----------------
__device__ __forceinline__ uint32_t sm_addr(const void* p) {
    return (uint32_t)__cvta_generic_to_shared(p);
}
__device__ __forceinline__ uint32_t f2tf32(float x) {
    uint32_t r; asm("cvt.rna.tf32.f32 %0, %1;" : "=r"(r) : "f"(x)); return r;
}
// 3xTF32 split: x = hi + lo (identical values to Round-15 kernel)
__device__ __forceinline__ void split_tf32(float x, uint32_t& hi, uint32_t& lo) {
    hi = f2tf32(x);
    lo = f2tf32(x - __uint_as_float(hi));
}
__device__ __forceinline__ uint32_t pack_bf16x2(float lo, float hi) {
    uint32_t d; asm("cvt.rn.bf16x2.f32 %0, %1, %2;" : "=r"(d) : "f"(hi), "f"(lo)); return d;
}
__device__ __forceinline__ void ldsm4(uint32_t& r0, uint32_t& r1, uint32_t& r2, uint32_t& r3, uint32_t a) {
    asm volatile("ldmatrix.sync.aligned.m8n8.x4.shared.b16 {%0,%1,%2,%3},[%4];"
                 : "=r"(r0), "=r"(r1), "=r"(r2), "=r"(r3) : "r"(a));
}
__device__ __forceinline__ void ldsm4t(uint32_t& r0, uint32_t& r1, uint32_t& r2, uint32_t& r3, uint32_t a) {
    asm volatile("ldmatrix.sync.aligned.m8n8.x4.trans.shared.b16 {%0,%1,%2,%3},[%4];"
                 : "=r"(r0), "=r"(r1), "=r"(r2), "=r"(r3) : "r"(a));
}
__device__ __forceinline__ void mma_bf16(float* c, const uint32_t* a, uint32_t b0, uint32_t b1) {
    asm volatile("mma.sync.aligned.m16n8k16.row.col.f32.bf16.bf16.f32 "
                 "{%0,%1,%2,%3},{%4,%5,%6,%7},{%8,%9},{%0,%1,%2,%3};"
                 : "+f"(c[0]), "+f"(c[1]), "+f"(c[2]), "+f"(c[3])
                 : "r"(a[0]), "r"(a[1]), "r"(a[2]), "r"(a[3]), "r"(b0), "r"(b1));
}
__device__ __forceinline__ void mma_tf32(float* c, const uint32_t* a, uint32_t b0, uint32_t b1) {
    asm volatile("mma.sync.aligned.m16n8k8.row.col.f32.tf32.tf32.f32 "
                 "{%0,%1,%2,%3},{%4,%5,%6,%7},{%8,%9},{%0,%1,%2,%3};"
                 : "+f"(c[0]), "+f"(c[1]), "+f"(c[2]), "+f"(c[3])
                 : "r"(a[0]), "r"(a[1]), "r"(a[2]), "r"(a[3]), "r"(b0), "r"(b1));
}
__device__ __forceinline__ void cp16(uint32_t dst, const void* src) {
    asm volatile("cp.async.cg.shared.global [%0],[%1],16;" :: "r"(dst), "l"(src) : "memory");
}
#define CP_COMMIT() asm volatile("cp.async.commit_group;" ::: "memory")
#define CP_WAIT0()  asm volatile("cp.async.wait_group 0;" ::: "memory")

// =====================================================================
// 3xTF32 GEMM core with PRE-SPLIT hi/lo smem planes.
// BM=128, BN=128, BK=32, 256 threads (8 warps 2x4).
// raw staging (cp.async) -> split once -> interleaved (hi,lo) planes
// mainloop: LDS.64 fetches hi+lo together; zero ALU in mainloop.
// =====================================================================
#define A_RAW_P 36      // raw A pitch (floats)
#define B_RAW_P 132     // raw B pitch (floats)
#define A_HL_P  76      // hi/lo A pitch (float slots; element e at 2e)
#define B_HL_P  264     // hi/lo B pitch
#define A_RAW_F (128 * A_RAW_P)
#define B_RAW_F (32 * B_RAW_P)
#define A_HL_F  (128 * A_HL_P)
#define B_HL_F  (32 * B_HL_P)
#define GEMM_SMEM_BYTES ((A_RAW_F + B_RAW_F + A_HL_F + B_HL_F) * 4)

struct GemmFrag { float acc[4][4][4]; };

// stage raw fp32 tile into smem via cp.async
__device__ __forceinline__ void gemm_stage_tile(
    float* Araw, float* Braw, const float* X, const float* W, int N, int k0, int col0, int tid)
{
    #pragma unroll
    for (int i = 0; i < 4; i++) {
        int idx = tid + i * 256;
        int ar = idx >> 3, ac4 = (idx & 7) << 2;
        cp16(sm_addr(&Araw[ar * A_RAW_P + ac4]), X + (size_t)ar * DIMIN + k0 + ac4);
    }
    #pragma unroll
    for (int i = 0; i < 4; i++) {
        int idx = tid + i * 256;
        int br = idx >> 5, bc4 = (idx & 31) << 2;
        cp16(sm_addr(&Braw[br * B_RAW_P + bc4]), W + (size_t)(k0 + br) * N + col0 + bc4);
    }
}

// split staged tile into interleaved (hi,lo) planes
__device__ __forceinline__ void gemm_split_tile(
    const float* Araw, const float* Braw, float* Ahl, float* Bhl, int tid)
{
    #pragma unroll
    for (int i = 0; i < 4; i++) {
        int idx = tid + i * 256;
        int ar = idx >> 3, ac4 = (idx & 7) << 2;
        float4 v = *reinterpret_cast<const float4*>(&Araw[ar * A_RAW_P + ac4]);
        uint32_t h0, l0, h1, l1, h2, l2, h3, l3;
        split_tf32(v.x, h0, l0); split_tf32(v.y, h1, l1);
        split_tf32(v.z, h2, l2); split_tf32(v.w, h3, l3);
        float* dst = &Ahl[ar * A_HL_P + 2 * ac4];
        *reinterpret_cast<uint4*>(dst)     = make_uint4(h0, l0, h1, l1);
        *reinterpret_cast<uint4*>(dst + 4) = make_uint4(h2, l2, h3, l3);
    }
    #pragma unroll
    for (int i = 0; i < 4; i++) {
        int idx = tid + i * 256;
        int br = idx >> 5, bc4 = (idx & 31) << 2;
        float4 v = *reinterpret_cast<const float4*>(&Braw[br * B_RAW_P + bc4]);
        uint32_t h0, l0, h1, l1, h2, l2, h3, l3;
        split_tf32(v.x, h0, l0); split_tf32(v.y, h1, l1);
        split_tf32(v.z, h2, l2); split_tf32(v.w, h3, l3);
        float* dst = &Bhl[br * B_HL_P + 2 * bc4];
        *reinterpret_cast<uint4*>(dst)     = make_uint4(h0, l0, h1, l1);
        *reinterpret_cast<uint4*>(dst + 4) = make_uint4(h2, l2, h3, l3);
    }
}

__device__ __forceinline__ void hl_load(const float* p, uint32_t& hi, uint32_t& lo)
{
    float2 v = *reinterpret_cast<const float2*>(p);
    hi = __float_as_uint(v.x);
    lo = __float_as_uint(v.y);
}

__device__ __forceinline__ void gemm_compute_tile(
    const float* Ahl, const float* Bhl, GemmFrag& F, int wr, int wc, int g, int t4)
{
    #pragma unroll
    for (int ks = 0; ks < 4; ks++) {
        const int kk = ks * 8 + t4;
        uint32_t ah[4][4], al[4][4], bh[4][2], bl[4][2];
        #pragma unroll
        for (int mi = 0; mi < 4; mi++) {
            const float* Ab = Ahl + (wr * 64 + mi * 16 + g) * A_HL_P;
            hl_load(Ab + 2 * kk,                  ah[mi][0], al[mi][0]);
            hl_load(Ab + 8 * A_HL_P + 2 * kk,     ah[mi][1], al[mi][1]);
            hl_load(Ab + 2 * (kk + 4),            ah[mi][2], al[mi][2]);
            hl_load(Ab + 8 * A_HL_P + 2 * (kk + 4), ah[mi][3], al[mi][3]);
        }
        #pragma unroll
        for (int ni = 0; ni < 4; ni++) {
            int n = wc * 32 + ni * 8 + g;
            hl_load(Bhl + kk * B_HL_P + 2 * n,       bh[ni][0], bl[ni][0]);
            hl_load(Bhl + (kk + 4) * B_HL_P + 2 * n, bh[ni][1], bl[ni][1]);
        }
        #pragma unroll
        for (int mi = 0; mi < 4; mi++)
            #pragma unroll
            for (int ni = 0; ni < 4; ni++) {
                mma_tf32(F.acc[mi][ni], ah[mi], bh[ni][0], bh[ni][1]);
                mma_tf32(F.acc[mi][ni], al[mi], bh[ni][0], bh[ni][1]);
                mma_tf32(F.acc[mi][ni], ah[mi], bl[ni][0], bl[ni][1]);
            }
    }
}

// ---------------- QKV projection ----------------
__global__ void __launch_bounds__(256, 2) gemm_qkv_kernel(
    const float* __restrict__ vid, const float* __restrict__ txt,
    const float* __restrict__ Wv, const float* __restrict__ bv,
    const float* __restrict__ Wt, const float* __restrict__ bt)
{
    extern __shared__ __align__(16) float smem[];
    float* Araw = smem;
    float* Braw = Araw + A_RAW_F;
    float* Ahl  = Braw + B_RAW_F;
    float* Bhl  = Ahl + A_HL_F;

    const int row0 = blockIdx.y * 128;
    const int col0 = blockIdx.x * 128;
    const int b = row0 >> 11;
    const int l0 = row0 & 2047;

    const float* X; const float* W; const float* bias;
    if (l0 < LV) { X = vid + (size_t)(b * LV + l0) * DIMIN;        W = Wv; bias = bv; }
    else         { X = txt + (size_t)(b * LT + (l0 - LV)) * DIMIN; W = Wt; bias = bt; }

    const int tid = threadIdx.x;
    const int wid = tid >> 5, lane = tid & 31;
    const int wr = wid >> 2, wc = wid & 3;
    const int g = lane >> 2, t4 = lane & 3;

    GemmFrag F;
    #pragma unroll
    for (int mi = 0; mi < 4; mi++)
        #pragma unroll
        for (int ni = 0; ni < 4; ni++)
            #pragma unroll
            for (int q = 0; q < 4; q++) F.acc[mi][ni][q] = 0.0f;

    const int NKT = DIMIN / 32;
    gemm_stage_tile(Araw, Braw, X, W, QKVN, 0, col0, tid);
    CP_COMMIT();

    for (int t = 0; t < NKT; t++) {
        CP_WAIT0();
        __syncthreads();                       // raw(t) visible; prev compute done
        gemm_split_tile(Araw, Braw, Ahl, Bhl, tid);
        __syncthreads();                       // planes ready; staging reads done
        if (t + 1 < NKT) {
            gemm_stage_tile(Araw, Braw, X, W, QKVN, (t + 1) * 32, col0, tid);
            CP_COMMIT();
        }
        gemm_compute_tile(Ahl, Bhl, F, wr, wc, g, t4);
    }

    #pragma unroll
    for (int mi = 0; mi < 4; mi++) {
        #pragma unroll
        for (int ni = 0; ni < 4; ni++) {
            int gr = row0 + wr * 64 + mi * 16 + g;
            int gc = col0 + wc * 32 + ni * 8 + 2 * t4;
            float2 bb = *reinterpret_cast<const float2*>(&bias[gc]);
            float2 o0 = make_float2(F.acc[mi][ni][0] + bb.x, F.acc[mi][ni][1] + bb.y);
            float2 o1 = make_float2(F.acc[mi][ni][2] + bb.x, F.acc[mi][ni][3] + bb.y);
            *reinterpret_cast<float2*>(&g_qkv[(size_t)gr * QKVN + gc]) = o0;
            *reinterpret_cast<float2*>(&g_qkv[(size_t)(gr + 8) * QKVN + gc]) = o1;
        }
    }
}

// ---------------- output projection ----------------
__global__ void __launch_bounds__(256, 2) gemm_out_kernel(
    const float* __restrict__ Wv, const float* __restrict__ bv,
    const float* __restrict__ Wt, const float* __restrict__ bt,
    float* __restrict__ out)
{
    extern __shared__ __align__(16) float smem[];
    float* Araw = smem;
    float* Braw = Araw + A_RAW_F;
    float* Ahl  = Braw + B_RAW_F;
    float* Bhl  = Ahl + A_HL_F;

    const int row0 = blockIdx.y * 128;
    const int col0 = blockIdx.x * 128;
    const int b = row0 >> 11;
    const int l0 = row0 & 2047;

    const float* W; const float* bias; float* O;
    if (l0 < LV) { W = Wv; bias = bv; O = out + (size_t)(b * LV + l0) * DIMIN; }
    else         { W = Wt; bias = bt;
                   O = out + (size_t)BATCH * LV * DIMIN + (size_t)(b * LT + (l0 - LV)) * DIMIN; }
    const float* X = g_attn + (size_t)row0 * DIMIN;

    const int tid = threadIdx.x;
    const int wid = tid >> 5, lane = tid & 31;
    const int wr = wid >> 2, wc = wid & 3;
    const int g = lane >> 2, t4 = lane & 3;

    GemmFrag F;
    #pragma unroll
    for (int mi = 0; mi < 4; mi++)
        #pragma unroll
        for (int ni = 0; ni < 4; ni++)
            #pragma unroll
            for (int q = 0; q < 4; q++) F.acc[mi][ni][q] = 0.0f;

    const int NKT = DIMIN / 32;
    gemm_stage_tile(Araw, Braw, X, W, DIMIN, 0, col0, tid);
    CP_COMMIT();

    for (int t = 0; t < NKT; t++) {
        CP_WAIT0();
        __syncthreads();
        gemm_split_tile(Araw, Braw, Ahl, Bhl, tid);
        __syncthreads();
        if (t + 1 < NKT) {
            gemm_stage_tile(Araw, Braw, X, W, DIMIN, (t + 1) * 32, col0, tid);
            CP_COMMIT();
        }
        gemm_compute_tile(Ahl, Bhl, F, wr, wc, g, t4);
    }

    #pragma unroll
    for (int mi = 0; mi < 4; mi++) {
        #pragma unroll
        for (int ni = 0; ni < 4; ni++) {
            int lr = wr * 64 + mi * 16 + g;
            int gc = col0 + wc * 32 + ni * 8 + 2 * t4;
            float2 bb = *reinterpret_cast<const float2*>(&bias[gc]);
            float2 o0 = make_float2(F.acc[mi][ni][0] + bb.x, F.acc[mi][ni][1] + bb.y);
            float2 o1 = make_float2(F.acc[mi][ni][2] + bb.x, F.acc[mi][ni][3] + bb.y);
            *reinterpret_cast<float2*>(&O[(size_t)lr * DIMIN + gc]) = o0;
            *reinterpret_cast<float2*>(&O[(size_t)(lr + 8) * DIMIN + gc]) = o1;
        }
    }
}

// =====================================================================
// RMSNorm + bf16 pack (unchanged)
// =====================================================================
__global__ void __launch_bounds__(128) norm_pack_kernel(
    const float* __restrict__ nq_vid, const float* __restrict__ nk_vid,
    const float* __restrict__ nq_txt, const float* __restrict__ nk_txt)
{
    const int h = blockIdx.x;
    const int t = blockIdx.y;
    const int d = threadIdx.x;
    const int b = t >> 11, l = t & 2047;
    const bool is_vid = (l < LV);

    const float* base = g_qkv + (size_t)t * QKVN + h * HD;
    float xq = base[d];
    float xk = base[DIMIN + d];
    float xv = base[2 * DIMIN + d];

    float sq = xq * xq, sk = xk * xk;
    #pragma unroll
    for (int o = 16; o; o >>= 1) {
        sq += __shfl_down_sync(0xffffffffu, sq, o);
        sk += __shfl_down_sync(0xffffffffu, sk, o);
    }
    __shared__ float shq[4], shk[4];
    const int wid = d >> 5, lane = d & 31;
    if (lane == 0) { shq[wid] = sq; shk[wid] = sk; }
    __syncthreads();
    float tq = shq[0] + shq[1] + shq[2] + shq[3];
    float tk = shk[0] + shk[1] + shk[2] + shk[3];
    float rq = rsqrtf(tq * (1.0f / HD) + EPSV);
    float rk = rsqrtf(tk * (1.0f / HD) + EPSV);

    float wq = is_vid ? nq_vid[d] : nq_txt[d];
    float wk = is_vid ? nk_vid[d] : nk_txt[d];

    size_t o = ((size_t)(b * NH + h) * LSEQ + l) * HD + d;
    g_q[o] = __float2bfloat16(xq * rq * wq);
    g_k[o] = __float2bfloat16(xk * rk * wk);
    g_v[o] = __float2bfloat16(xv);
}

// =====================================================================
// Attention: bf16 mma, two-pass exact softmax with bf16 probs (unchanged)
// =====================================================================
#define APAD 136
#define ATT_SMEM_BYTES (3 * 64 * APAD * 2)

__device__ __forceinline__ void att_load_tile(__nv_bfloat16* dst,
                                              const __nv_bfloat16* src, int tid)
{
    #pragma unroll
    for (int i = 0; i < 8; i++) {
        int idx = tid + i * 128;
        int r = idx >> 4, c8 = (idx & 15) << 3;
        cp16(sm_addr(&dst[r * APAD + c8]), src + (size_t)r * HD + c8);
    }
}

__global__ void __launch_bounds__(128) attn_mma_kernel()
{
    extern __shared__ __align__(16) char smem_raw[];
    __nv_bfloat16* sQ = reinterpret_cast<__nv_bfloat16*>(smem_raw);
    __nv_bfloat16* sK = sQ + 64 * APAD;
    __nv_bfloat16* sV = sK + 64 * APAD;

    const int qt = blockIdx.x, h = blockIdx.y, b = blockIdx.z;
    const int tid = threadIdx.x, wid = tid >> 5, lane = tid & 31;
    const int g = lane >> 2, t4 = lane & 3;
    const float scale = 0.08838834764831845f;

    const size_t headbase = (size_t)(b * NH + h) * LSEQ * HD;
    const __nv_bfloat16* Qg = g_q + headbase + (size_t)qt * 64 * HD;
    const __nv_bfloat16* Kg = g_k + headbase;
    const __nv_bfloat16* Vg = g_v + headbase;

    att_load_tile(sQ, Qg, tid);
    CP_COMMIT(); CP_WAIT0();
    __syncthreads();

    uint32_t qa[8][4];
    {
        int row = wid * 16 + (lane & 15);
        int coff = (lane >> 4) << 3;
        #pragma unroll
        for (int kb = 0; kb < 8; kb++)
            ldsm4(qa[kb][0], qa[kb][1], qa[kb][2], qa[kb][3],
                  sm_addr(&sQ[row * APAD + kb * 16 + coff]));
    }

    float m0r = -CUDART_INF_F, m1r = -CUDART_INF_F, l0r = 0.0f, l1r = 0.0f;

    const int k_row = (lane & 7) + ((lane >> 4) << 3);
    const int k_coff = ((lane >> 3) & 1) << 3;
    const int v_row = (lane & 7) + (((lane >> 3) & 1) << 3);
    const int v_coff = (lane >> 4) << 3;

    // ---------------- pass 1 ----------------
    for (int kt = 0; kt < LSEQ / 64; kt++) {
        __syncthreads();
        att_load_tile(sK, Kg + (size_t)kt * 64 * HD, tid);
        CP_COMMIT(); CP_WAIT0();
        __syncthreads();

        float s[8][4];
        #pragma unroll
        for (int j = 0; j < 8; j++)
            #pragma unroll
            for (int q = 0; q < 4; q++) s[j][q] = 0.0f;

        #pragma unroll
        for (int kb = 0; kb < 8; kb++) {
            #pragma unroll
            for (int nn = 0; nn < 4; nn++) {
                uint32_t b0, b1, b2, b3;
                ldsm4(b0, b1, b2, b3,
                      sm_addr(&sK[(nn * 16 + k_row) * APAD + kb * 16 + k_coff]));
                mma_bf16(s[2 * nn],     qa[kb], b0, b1);
                mma_bf16(s[2 * nn + 1], qa[kb], b2, b3);
            }
        }

        float mt0 = -CUDART_INF_F, mt1 = -CUDART_INF_F;
        #pragma unroll
        for (int j = 0; j < 8; j++) {
            mt0 = fmaxf(mt0, fmaxf(s[j][0], s[j][1]));
            mt1 = fmaxf(mt1, fmaxf(s[j][2], s[j][3]));
        }
        mt0 = fmaxf(mt0, __shfl_xor_sync(0xffffffffu, mt0, 1));
        mt0 = fmaxf(mt0, __shfl_xor_sync(0xffffffffu, mt0, 2));
        mt1 = fmaxf(mt1, __shfl_xor_sync(0xffffffffu, mt1, 1));
        mt1 = fmaxf(mt1, __shfl_xor_sync(0xffffffffu, mt1, 2));
        float mn0 = fmaxf(m0r, mt0 * scale);
        float mn1 = fmaxf(m1r, mt1 * scale);
        float sum0 = 0.0f, sum1 = 0.0f;
        #pragma unroll
        for (int j = 0; j < 8; j++) {
            sum0 += __expf(s[j][0] * scale - mn0) + __expf(s[j][1] * scale - mn0);
            sum1 += __expf(s[j][2] * scale - mn1) + __expf(s[j][3] * scale - mn1);
        }
        sum0 += __shfl_xor_sync(0xffffffffu, sum0, 1);
        sum0 += __shfl_xor_sync(0xffffffffu, sum0, 2);
        sum1 += __shfl_xor_sync(0xffffffffu, sum1, 1);
        sum1 += __shfl_xor_sync(0xffffffffu, sum1, 2);
        l0r = l0r * __expf(m0r - mn0) + sum0;  m0r = mn0;
        l1r = l1r * __expf(m1r - mn1) + sum1;  m1r = mn1;
    }

    const float linv0 = 1.0f / l0r;
    const float linv1 = 1.0f / l1r;

    // ---------------- pass 2 ----------------
    float oacc[16][4];
    #pragma unroll
    for (int j = 0; j < 16; j++)
        #pragma unroll
        for (int q = 0; q < 4; q++) oacc[j][q] = 0.0f;

    for (int kt = 0; kt < LSEQ / 64; kt++) {
        __syncthreads();
        att_load_tile(sK, Kg + (size_t)kt * 64 * HD, tid);
        att_load_tile(sV, Vg + (size_t)kt * 64 * HD, tid);
        CP_COMMIT(); CP_WAIT0();
        __syncthreads();

        float s[8][4];
        #pragma unroll
        for (int j = 0; j < 8; j++)
            #pragma unroll
            for (int q = 0; q < 4; q++) s[j][q] = 0.0f;

        #pragma unroll
        for (int kb = 0; kb < 8; kb++) {
            #pragma unroll
            for (int nn = 0; nn < 4; nn++) {
                uint32_t b0, b1, b2, b3;
                ldsm4(b0, b1, b2, b3,
                      sm_addr(&sK[(nn * 16 + k_row) * APAD + kb * 16 + k_coff]));
                mma_bf16(s[2 * nn],     qa[kb], b0, b1);
                mma_bf16(s[2 * nn + 1], qa[kb], b2, b3);
            }
        }

        uint32_t pa[4][4];
        #pragma unroll
        for (int j = 0; j < 8; j++) {
            float p0 = __expf(s[j][0] * scale - m0r) * linv0;
            float p1 = __expf(s[j][1] * scale - m0r) * linv0;
            float p2 = __expf(s[j][2] * scale - m1r) * linv1;
            float p3 = __expf(s[j][3] * scale - m1r) * linv1;
            int kb = j >> 1, half = j & 1;
            pa[kb][2 * half + 0] = pack_bf16x2(p0, p1);
            pa[kb][2 * half + 1] = pack_bf16x2(p2, p3);
        }

        #pragma unroll
        for (int kb = 0; kb < 4; kb++) {
            #pragma unroll
            for (int nn = 0; nn < 8; nn++) {
                uint32_t v0, v1, v2, v3;
                ldsm4t(v0, v1, v2, v3,
                       sm_addr(&sV[(kb * 16 + v_row) * APAD + nn * 16 + v_coff]));
                mma_bf16(oacc[2 * nn],     pa[kb], v0, v1);
                mma_bf16(oacc[2 * nn + 1], pa[kb], v2, v3);
            }
        }
    }

    const size_t trow0 = (size_t)b * LSEQ + qt * 64 + wid * 16;
    #pragma unroll
    for (int j = 0; j < 16; j++) {
        int c = h * HD + j * 8 + 2 * t4;
        float2 o0 = make_float2(oacc[j][0], oacc[j][1]);
        float2 o1 = make_float2(oacc[j][2], oacc[j][3]);
        *reinterpret_cast<float2*>(&g_attn[(trow0 + g) * DIMIN + c]) = o0;
        *reinterpret_cast<float2*>(&g_attn[(trow0 + g + 8) * DIMIN + c]) = o1;
    }
}

// =====================================================================
extern "C" void kernel_launch(void* const* d_in, const int* in_sizes, int n_in,
                              void* d_out, int out_size)
{
    const float* vid      = (const float*)d_in[0];
    const float* txt      = (const float*)d_in[1];
    const float* Wqkv_vid = (const float*)d_in[2];
    const float* bqkv_vid = (const float*)d_in[3];
    const float* Wqkv_txt = (const float*)d_in[4];
    const float* bqkv_txt = (const float*)d_in[5];
    const float* nq_vid   = (const float*)d_in[6];
    const float* nk_vid   = (const float*)d_in[7];
    const float* nq_txt   = (const float*)d_in[8];
    const float* nk_txt   = (const float*)d_in[9];
    const float* Wout_vid = (const float*)d_in[10];
    const float* bout_vid = (const float*)d_in[11];
    const float* Wout_txt = (const float*)d_in[12];
    const float* bout_txt = (const float*)d_in[13];
    float* out = (float*)d_out;

    cudaFuncSetAttribute(gemm_qkv_kernel, cudaFuncAttributeMaxDynamicSharedMemorySize, GEMM_SMEM_BYTES);
    cudaFuncSetAttribute(gemm_out_kernel, cudaFuncAttributeMaxDynamicSharedMemorySize, GEMM_SMEM_BYTES);
    cudaFuncSetAttribute(attn_mma_kernel, cudaFuncAttributeMaxDynamicSharedMemorySize, ATT_SMEM_BYTES);

    gemm_qkv_kernel<<<dim3(QKVN / 128, NTOK / 128), 256, GEMM_SMEM_BYTES>>>(
        vid, txt, Wqkv_vid, bqkv_vid, Wqkv_txt, bqkv_txt);

    norm_pack_kernel<<<dim3(NH, NTOK), 128>>>(nq_vid, nk_vid, nq_txt, nk_txt);

    attn_mma_kernel<<<dim3(LSEQ / 64, NH, BATCH), 128, ATT_SMEM_BYTES>>>();

    gemm_out_kernel<<<dim3(DIMIN / 128, NTOK / 128), 256, GEMM_SMEM_BYTES>>>(
        Wout_vid, bout_vid, Wout_txt, bout_txt, out);
}